// round 6
// baseline (speedup 1.0000x reference)
#include <cuda_runtime.h>

#define RES 512
#define NBLOBS 2048
#define TILE_X 32
#define TILE_Y 16
#define BXD 32
#define BYD 4
#define NT 128           // threads per CTA
#define PPT 4            // pixels per thread (stride BYD rows)
#define QCUT 4.5f        // cutoff in sigma units; exp(-10.125) ~ 4e-5

// Scratch (no allocations allowed): per-blob cull box + derived params.
__device__ float4 g_cull[NBLOBS];          // (bx, by, ex, ey)
__device__ float4 g_parm[NBLOBS * 3];      // (bx,by,A,B) (C,D,m1,m2) (r,g,b,c0)

// ---------------------------------------------------------------------------
// Prep: per-blob derived parameters.
//   a = (c*dx + s*dy) * kk/sx ,  b = (-s*dx + c*dy) * kk/sy , kk = sqrt(0.5*log2e)
//   g = exp(-0.5*((xr/sx)^2+(yr/sy)^2)) = 2^(-(a^2+b^2))
// Second-difference constants for y-stepping by dlt = BYD/RES:
//   t(k) = -(a+k*da)^2-(b+k*db)^2 :  d0 = m1*a+m2*b+c0, dd = 2*c0
// ---------------------------------------------------------------------------
__global__ void splat_prep_kernel(const float* __restrict__ blobs) {
    int i = blockIdx.x * blockDim.x + threadIdx.x;
    if (i >= NBLOBS) return;
    const float* bl = blobs + i * 8;
    float bx = bl[0], by = bl[1];
    float sx = bl[2], sy = bl[3];
    float rot = bl[4];
    float cr = bl[5], cg = bl[6], cb = bl[7];

    float s, c;
    sincosf(rot, &s, &c);

    const float kk = 0.84932180f;      // sqrt(0.5 * log2(e))
    float isx = kk / sx;
    float isy = kk / sy;
    float A = c * isx, B = s * isx;    // a = A*dx + B*dy
    float C = -s * isy, D = c * isy;   // b = C*dx + D*dy

    const float dlt = (float)BYD / (float)RES;
    float da = B * dlt;
    float db = D * dlt;
    float m1 = -2.0f * da;
    float m2 = -2.0f * db;
    float c0 = -(da * da + db * db);

    // AABB half-extents of the QCUT-sigma ellipse
    float ex = QCUT * sqrtf(c * c * sx * sx + s * s * sy * sy);
    float ey = QCUT * sqrtf(s * s * sx * sx + c * c * sy * sy);

    g_cull[i] = make_float4(bx, by, ex, ey);
    g_parm[i * 3 + 0] = make_float4(bx, by, A, B);
    g_parm[i * 3 + 1] = make_float4(C, D, m1, m2);
    g_parm[i * 3 + 2] = make_float4(cr, cg, cb, c0);
}

// ---------------------------------------------------------------------------
// Render: one CTA per 32x16 tile; 128 threads (32x4); 4 pixels/thread.
// Pipeline: batch-N params live in registers while batch-N+1 LDGs are in
// flight behind the j-loop. Order-preserving ballot/prefix compaction of
// survivors into shared; survivor list padded to even length; 2-way unrolled
// evaluation with warp-uniform negligibility skip.
// ---------------------------------------------------------------------------
__global__ void __launch_bounds__(NT) splat_render_kernel(float* __restrict__ out) {
    __shared__ float4 sP[NT + 1][3];
    __shared__ int sWarp[NT / 32];

    const int tx = threadIdx.x;            // 0..31
    const int ty = threadIdx.y;            // 0..3
    const int tid = ty * BXD + tx;
    const int lane = tid & 31;
    const int wid = tid >> 5;

    const int x = blockIdx.x * TILE_X + tx;
    const int y0 = blockIdx.y * TILE_Y + ty;
    const float inv = 1.0f / (float)RES;
    const float px = ((float)x + 0.5f) * inv;
    const float py = ((float)y0 + 0.5f) * inv;

    const float tX0 = (float)blockIdx.x * ((float)TILE_X * inv);
    const float tX1 = tX0 + (float)TILE_X * inv;
    const float tY0 = (float)blockIdx.y * ((float)TILE_Y * inv);
    const float tY1 = tY0 + (float)TILE_Y * inv;

    float aR[PPT], aG[PPT], aB[PPT];
#pragma unroll
    for (int k = 0; k < PPT; ++k) { aR[k] = 0.0f; aG[k] = 0.0f; aB[k] = 0.0f; }

    // Prefetch batch 0 into registers.
    float4 cu = g_cull[tid];
    float4 q0 = g_parm[tid * 3 + 0];
    float4 q1 = g_parm[tid * 3 + 1];
    float4 q2 = g_parm[tid * 3 + 2];

    for (int base = 0; base < NBLOBS; base += NT) {
        const bool keep = (cu.x + cu.z >= tX0) && (cu.x - cu.z <= tX1) &&
                          (cu.y + cu.w >= tY0) && (cu.y - cu.w <= tY1);

        const unsigned m = __ballot_sync(0xffffffffu, keep);
        if (lane == 0) sWarp[wid] = __popc(m);
        __syncthreads();

        int off = 0, total = 0;
#pragma unroll
        for (int w = 0; w < NT / 32; ++w) {
            int cw = sWarp[w];
            if (w < wid) off += cw;
            total += cw;
        }

        if (keep) {
            const int slot = off + __popc(m & ((1u << lane) - 1u));
            sP[slot][0] = q0;
            sP[slot][1] = q1;
            sP[slot][2] = q2;
        }
        // Pad survivor list to even length with a zero-color dummy.
        if (tid == 0 && (total & 1)) {
            const float4 z = make_float4(0.0f, 0.0f, 0.0f, 0.0f);
            sP[total][0] = z;
            sP[total][1] = z;
            sP[total][2] = z;
        }
        __syncthreads();

        // Prefetch next batch (latency hidden behind the j-loop below).
        const int nb = base + NT;
        if (nb < NBLOBS) {
            const int i2 = nb + tid;
            cu = g_cull[i2];
            q0 = g_parm[i2 * 3 + 0];
            q1 = g_parm[i2 * 3 + 1];
            q2 = g_parm[i2 * 3 + 2];
        }

        const int tp = (total + 1) & ~1;

#define PAIR_BODY(J)                                                          \
        {                                                                     \
            const float4 p0 = sP[(J)][0];                                     \
            const float4 p1 = sP[(J)][1];                                     \
            const float4 p2 = sP[(J)][2];                                     \
            const float dx = px - p0.x;                                       \
            const float dy = py - p0.y;                                       \
            float a = fmaf(p0.z, dx, p0.w * dy);                              \
            float b = fmaf(p1.x, dx, p1.y * dy);                              \
            float t = fmaf(a, -a, -b * b);                                    \
            float d = fmaf(a, p1.z, fmaf(b, p1.w, p2.w));                     \
            const float ub = fmaf(3.0f, fmaxf(d, 0.0f), t);                   \
            if (!__all_sync(0xffffffffu, ub < -15.0f)) {                      \
                const float dd = p2.w + p2.w;                                 \
                _Pragma("unroll")                                             \
                for (int k = 0; k < PPT; ++k) {                               \
                    float g;                                                  \
                    asm("ex2.approx.ftz.f32 %0, %1;" : "=f"(g) : "f"(t));     \
                    aR[k] = fmaf(g, p2.x, aR[k]);                             \
                    aG[k] = fmaf(g, p2.y, aG[k]);                             \
                    aB[k] = fmaf(g, p2.z, aB[k]);                             \
                    if (k < PPT - 1) { t += d; d += dd; }                     \
                }                                                             \
            }                                                                 \
        }

        for (int j = 0; j < tp; j += 2) {
            PAIR_BODY(j)
            PAIR_BODY(j + 1)
        }
#undef PAIR_BODY

        __syncthreads();  // protect sP / sWarp before next batch rewrites them
    }

    int idx = (y0 * RES + x) * 3;
#pragma unroll
    for (int k = 0; k < PPT; ++k) {
        out[idx + 0] = aR[k];
        out[idx + 1] = aG[k];
        out[idx + 2] = aB[k];
        idx += BYD * RES * 3;
    }
}

extern "C" void kernel_launch(void* const* d_in, const int* in_sizes, int n_in,
                              void* d_out, int out_size) {
    (void)in_sizes; (void)n_in; (void)out_size;
    const float* blobs = (const float*)d_in[0];
    float* out = (float*)d_out;

    splat_prep_kernel<<<NBLOBS / 256, 256>>>(blobs);
    dim3 grid(RES / TILE_X, RES / TILE_Y);   // 16 x 32 tiles
    dim3 block(BXD, BYD);
    splat_render_kernel<<<grid, block>>>(out);
}

// round 7
// speedup vs baseline: 1.1982x; 1.1982x over previous
#include <cuda_runtime.h>

#define RES 512
#define NBLOBS 2048
#define TILE_X 32
#define TILE_Y 16
#define BXD 32
#define BYD 4
#define NT 128           // threads per CTA
#define PPT 4            // pixels per thread (stride BYD rows)
#define QCUT 4.5f        // cutoff in sigma units; exp(-10.125) ~ 4e-5

// Scratch (no allocations allowed): per-blob cull box + derived params.
__device__ float4 g_cull[NBLOBS];          // (bx, by, ex, ey)
__device__ float4 g_parm[NBLOBS * 3];      // (bx,by,A,B) (C,D,m1,m2) (r,g,b,c0)

// ---------------------------------------------------------------------------
// Prep: per-blob derived parameters.
//   a = (c*dx + s*dy) * kk/sx ,  b = (-s*dx + c*dy) * kk/sy , kk = sqrt(0.5*log2e)
//   g = exp(-0.5*((xr/sx)^2+(yr/sy)^2)) = 2^(-(a^2+b^2))
// Second-difference constants for y-stepping by dlt = BYD/RES:
//   t(k) = -(a+k*da)^2-(b+k*db)^2 :  d0 = m1*a+m2*b+c0, dd = 2*c0
// ---------------------------------------------------------------------------
__global__ void splat_prep_kernel(const float* __restrict__ blobs) {
    int i = blockIdx.x * blockDim.x + threadIdx.x;
    if (i >= NBLOBS) return;
    const float* bl = blobs + i * 8;
    float bx = bl[0], by = bl[1];
    float sx = bl[2], sy = bl[3];
    float rot = bl[4];
    float cr = bl[5], cg = bl[6], cb = bl[7];

    float s, c;
    sincosf(rot, &s, &c);

    const float kk = 0.84932180f;      // sqrt(0.5 * log2(e))
    float isx = kk / sx;
    float isy = kk / sy;
    float A = c * isx, B = s * isx;    // a = A*dx + B*dy
    float C = -s * isy, D = c * isy;   // b = C*dx + D*dy

    const float dlt = (float)BYD / (float)RES;
    float da = B * dlt;
    float db = D * dlt;
    float m1 = -2.0f * da;
    float m2 = -2.0f * db;
    float c0 = -(da * da + db * db);

    // AABB half-extents of the QCUT-sigma ellipse
    float ex = QCUT * sqrtf(c * c * sx * sx + s * s * sy * sy);
    float ey = QCUT * sqrtf(s * s * sx * sx + c * c * sy * sy);

    g_cull[i] = make_float4(bx, by, ex, ey);
    g_parm[i * 3 + 0] = make_float4(bx, by, A, B);
    g_parm[i * 3 + 1] = make_float4(C, D, m1, m2);
    g_parm[i * 3 + 2] = make_float4(cr, cg, cb, c0);
}

// ---------------------------------------------------------------------------
// Render: one CTA per 32x16 tile; 128 threads (32x4); 4 pixels/thread.
// Register prefetch of batch N+1 hides global latency behind batch N's j-loop.
// Order-preserving ballot/prefix compaction of survivors into shared, then
// 2-way-unrolled evaluation (two independent pair pipelines per warp).
// ---------------------------------------------------------------------------
__global__ void __launch_bounds__(NT) splat_render_kernel(float* __restrict__ out) {
    __shared__ float4 sP[NT][3];
    __shared__ int sWarp[NT / 32];

    const int tx = threadIdx.x;            // 0..31
    const int ty = threadIdx.y;            // 0..3
    const int tid = ty * BXD + tx;
    const int lane = tid & 31;
    const int wid = tid >> 5;

    const int x = blockIdx.x * TILE_X + tx;
    const int y0 = blockIdx.y * TILE_Y + ty;
    const float inv = 1.0f / (float)RES;
    const float px = ((float)x + 0.5f) * inv;
    const float py = ((float)y0 + 0.5f) * inv;

    const float tX0 = (float)blockIdx.x * ((float)TILE_X * inv);
    const float tX1 = tX0 + (float)TILE_X * inv;
    const float tY0 = (float)blockIdx.y * ((float)TILE_Y * inv);
    const float tY1 = tY0 + (float)TILE_Y * inv;

    float aR[PPT], aG[PPT], aB[PPT];
#pragma unroll
    for (int k = 0; k < PPT; ++k) { aR[k] = 0.0f; aG[k] = 0.0f; aB[k] = 0.0f; }

    // Prefetch batch 0 into registers.
    float4 cu = g_cull[tid];
    float4 q0 = g_parm[tid * 3 + 0];
    float4 q1 = g_parm[tid * 3 + 1];
    float4 q2 = g_parm[tid * 3 + 2];

    for (int base = 0; base < NBLOBS; base += NT) {
        const bool keep = (cu.x + cu.z >= tX0) && (cu.x - cu.z <= tX1) &&
                          (cu.y + cu.w >= tY0) && (cu.y - cu.w <= tY1);

        const unsigned m = __ballot_sync(0xffffffffu, keep);
        if (lane == 0) sWarp[wid] = __popc(m);
        __syncthreads();

        int off = 0, total = 0;
#pragma unroll
        for (int w = 0; w < NT / 32; ++w) {
            int cw = sWarp[w];
            if (w < wid) off += cw;
            total += cw;
        }

        if (keep) {
            const int slot = off + __popc(m & ((1u << lane) - 1u));
            sP[slot][0] = q0;
            sP[slot][1] = q1;
            sP[slot][2] = q2;
        }
        __syncthreads();

        // Prefetch next batch (latency hidden behind the j-loop below).
        const int nb = base + NT;
        if (nb < NBLOBS) {
            const int i2 = nb + tid;
            cu = g_cull[i2];
            q0 = g_parm[i2 * 3 + 0];
            q1 = g_parm[i2 * 3 + 1];
            q2 = g_parm[i2 * 3 + 2];
        }

#define PAIR_BODY(J)                                                          \
        {                                                                     \
            const float4 p0 = sP[(J)][0];                                     \
            const float4 p1 = sP[(J)][1];                                     \
            const float4 p2 = sP[(J)][2];                                     \
            const float dx = px - p0.x;                                       \
            const float dy = py - p0.y;                                       \
            float a = fmaf(p0.z, dx, p0.w * dy);                              \
            float b = fmaf(p1.x, dx, p1.y * dy);                              \
            float t = fmaf(a, -a, -b * b);                                    \
            float d = fmaf(a, p1.z, fmaf(b, p1.w, p2.w));                     \
            const float dd = p2.w + p2.w;                                     \
            _Pragma("unroll")                                                 \
            for (int k = 0; k < PPT; ++k) {                                   \
                float g;                                                      \
                asm("ex2.approx.ftz.f32 %0, %1;" : "=f"(g) : "f"(t));         \
                aR[k] = fmaf(g, p2.x, aR[k]);                                 \
                aG[k] = fmaf(g, p2.y, aG[k]);                                 \
                aB[k] = fmaf(g, p2.z, aB[k]);                                 \
                if (k < PPT - 1) { t += d; d += dd; }                         \
            }                                                                 \
        }

        int j = 0;
        for (; j + 2 <= total; j += 2) {
            PAIR_BODY(j)
            PAIR_BODY(j + 1)
        }
        if (j < total) {
            PAIR_BODY(j)
        }
#undef PAIR_BODY

        __syncthreads();  // protect sP / sWarp before next batch rewrites them
    }

    int idx = (y0 * RES + x) * 3;
#pragma unroll
    for (int k = 0; k < PPT; ++k) {
        out[idx + 0] = aR[k];
        out[idx + 1] = aG[k];
        out[idx + 2] = aB[k];
        idx += BYD * RES * 3;
    }
}

extern "C" void kernel_launch(void* const* d_in, const int* in_sizes, int n_in,
                              void* d_out, int out_size) {
    (void)in_sizes; (void)n_in; (void)out_size;
    const float* blobs = (const float*)d_in[0];
    float* out = (float*)d_out;

    splat_prep_kernel<<<NBLOBS / 256, 256>>>(blobs);
    dim3 grid(RES / TILE_X, RES / TILE_Y);   // 16 x 32 tiles
    dim3 block(BXD, BYD);
    splat_render_kernel<<<grid, block>>>(out);
}

// round 8
// speedup vs baseline: 1.2699x; 1.0598x over previous
#include <cuda_runtime.h>

#define RES 512
#define NBLOBS 2048
#define HALF (NBLOBS / 2)
#define TILE_X 32
#define TILE_Y 16
#define BXD 32
#define BYD 4
#define NT 128           // threads per CTA
#define PPT 4            // pixels per thread (stride BYD rows)
#define QCUT 4.5f        // cutoff in sigma units; exp(-10.125) ~ 4e-5
#define NPIX (RES * RES * 3)

// Partial images for the two blob halves (no allocations allowed).
__device__ float4 g_partA[NPIX / 4];
__device__ float4 g_partB[NPIX / 4];

// ---------------------------------------------------------------------------
// Render: one CTA per (32x16 tile, blob-half). 128 threads (32x4); 4 px/thread.
// Per-batch: prefetch raw blob (2 float4), derive splat constants in-register,
// ballot/prefix-compact tile survivors into shared, 2-way-unrolled evaluation
// with a per-column second-difference recurrence for the exponent:
//   a = (c*dx + s*dy)*kk/sx, b = (-s*dx + c*dy)*kk/sy, kk = sqrt(0.5*log2e)
//   g = 2^(-(a^2+b^2));  stepping y by BYD/RES: t += d; d += dd
// ---------------------------------------------------------------------------
__global__ void __launch_bounds__(NT, 7) splat_render_kernel(const float* __restrict__ blobs) {
    __shared__ float4 sP[NT][3];
    __shared__ int sWarp[NT / 32];

    const int tx = threadIdx.x;            // 0..31
    const int ty = threadIdx.y;            // 0..3
    const int tid = ty * BXD + tx;
    const int lane = tid & 31;
    const int wid = tid >> 5;
    const int blobBase = blockIdx.z * HALF;
    float* __restrict__ dst = (float*)(blockIdx.z ? g_partB : g_partA);

    const int x = blockIdx.x * TILE_X + tx;
    const int y0 = blockIdx.y * TILE_Y + ty;
    const float inv = 1.0f / (float)RES;
    const float px = ((float)x + 0.5f) * inv;
    const float py = ((float)y0 + 0.5f) * inv;

    const float tX0 = (float)blockIdx.x * ((float)TILE_X * inv);
    const float tX1 = tX0 + (float)TILE_X * inv;
    const float tY0 = (float)blockIdx.y * ((float)TILE_Y * inv);
    const float tY1 = tY0 + (float)TILE_Y * inv;

    float aR[PPT], aG[PPT], aB[PPT];
#pragma unroll
    for (int k = 0; k < PPT; ++k) { aR[k] = 0.0f; aG[k] = 0.0f; aB[k] = 0.0f; }

    // Prefetch batch 0 raw blob (8 floats).
    const float4* __restrict__ blobs4 = (const float4*)blobs;
    float4 r0 = blobs4[(blobBase + tid) * 2 + 0];
    float4 r1 = blobs4[(blobBase + tid) * 2 + 1];

    for (int base = 0; base < HALF; base += NT) {
        // Derive splat constants for this thread's blob of the current batch.
        const float bx = r0.x, by = r0.y, sx = r0.z, sy = r0.w;
        const float rot = r1.x;
        float s, c;
        __sincosf(rot, &s, &c);
        const float kk = 0.84932180f;                  // sqrt(0.5*log2(e))
        const float isx = __fdividef(kk, sx);
        const float isy = __fdividef(kk, sy);
        const float A = c * isx, B = s * isx;
        const float C = -s * isy, D = c * isy;
        const float dlt = (float)BYD * inv;
        const float da = B * dlt, db = D * dlt;
        const float m1 = -2.0f * da, m2 = -2.0f * db;
        const float c0 = -(da * da + db * db);
        const float cc = c * c, ss = s * s;
        const float sx2 = sx * sx, sy2 = sy * sy;
        const float ex = QCUT * sqrtf(fmaf(cc, sx2, ss * sy2));
        const float ey = QCUT * sqrtf(fmaf(ss, sx2, cc * sy2));

        const bool keep = (bx + ex >= tX0) && (bx - ex <= tX1) &&
                          (by + ey >= tY0) && (by - ey <= tY1);

        const unsigned m = __ballot_sync(0xffffffffu, keep);
        if (lane == 0) sWarp[wid] = __popc(m);
        __syncthreads();

        int off = 0, total = 0;
#pragma unroll
        for (int w = 0; w < NT / 32; ++w) {
            int cw = sWarp[w];
            if (w < wid) off += cw;
            total += cw;
        }

        if (keep) {
            const int slot = off + __popc(m & ((1u << lane) - 1u));
            sP[slot][0] = make_float4(bx, by, A, B);
            sP[slot][1] = make_float4(C, D, m1, m2);
            sP[slot][2] = make_float4(r1.y, r1.z, r1.w, c0);
        }
        __syncthreads();

        // Prefetch next batch's raw blob (latency hidden behind the j-loop).
        const int nb = base + NT;
        if (nb < HALF) {
            const int i2 = blobBase + nb + tid;
            r0 = blobs4[i2 * 2 + 0];
            r1 = blobs4[i2 * 2 + 1];
        }

#define PAIR_BODY(J)                                                          \
        {                                                                     \
            const float4 p0 = sP[(J)][0];                                     \
            const float4 p1 = sP[(J)][1];                                     \
            const float4 p2 = sP[(J)][2];                                     \
            const float dx = px - p0.x;                                       \
            const float dy = py - p0.y;                                       \
            float a = fmaf(p0.z, dx, p0.w * dy);                              \
            float b = fmaf(p1.x, dx, p1.y * dy);                              \
            float t = fmaf(a, -a, -b * b);                                    \
            float d = fmaf(a, p1.z, fmaf(b, p1.w, p2.w));                     \
            const float dd = p2.w + p2.w;                                     \
            _Pragma("unroll")                                                 \
            for (int k = 0; k < PPT; ++k) {                                   \
                float g;                                                      \
                asm("ex2.approx.ftz.f32 %0, %1;" : "=f"(g) : "f"(t));         \
                aR[k] = fmaf(g, p2.x, aR[k]);                                 \
                aG[k] = fmaf(g, p2.y, aG[k]);                                 \
                aB[k] = fmaf(g, p2.z, aB[k]);                                 \
                if (k < PPT - 1) { t += d; d += dd; }                         \
            }                                                                 \
        }

        int j = 0;
        for (; j + 2 <= total; j += 2) {
            PAIR_BODY(j)
            PAIR_BODY(j + 1)
        }
        if (j < total) {
            PAIR_BODY(j)
        }
#undef PAIR_BODY

        __syncthreads();  // protect sP / sWarp before next batch rewrites them
    }

    int idx = (y0 * RES + x) * 3;
#pragma unroll
    for (int k = 0; k < PPT; ++k) {
        dst[idx + 0] = aR[k];
        dst[idx + 1] = aG[k];
        dst[idx + 2] = aB[k];
        idx += BYD * RES * 3;
    }
}

// ---------------------------------------------------------------------------
// Combine: out = partA + partB (float4 vectorized, DRAM-bound, ~1 us).
// ---------------------------------------------------------------------------
__global__ void splat_combine_kernel(float4* __restrict__ out) {
    const int i = blockIdx.x * blockDim.x + threadIdx.x;
    const float4 a = g_partA[i];
    const float4 b = g_partB[i];
    out[i] = make_float4(a.x + b.x, a.y + b.y, a.z + b.z, a.w + b.w);
}

extern "C" void kernel_launch(void* const* d_in, const int* in_sizes, int n_in,
                              void* d_out, int out_size) {
    (void)in_sizes; (void)n_in; (void)out_size;
    const float* blobs = (const float*)d_in[0];

    dim3 grid(RES / TILE_X, RES / TILE_Y, 2);   // 16 x 32 tiles x 2 blob halves
    dim3 block(BXD, BYD);
    splat_render_kernel<<<grid, block>>>(blobs);
    splat_combine_kernel<<<NPIX / 4 / 256, 256>>>((float4*)d_out);
}

// round 9
// speedup vs baseline: 1.2796x; 1.0077x over previous
#include <cuda_runtime.h>

#define RES 512
#define NBLOBS 2048
#define HALF (NBLOBS / 2)
#define TILE_X 32
#define TILE_Y 16
#define BXD 32
#define BYD 4
#define NT 128           // threads per CTA
#define PPT 4            // pixels per thread (stride BYD rows)
#define QCUT 4.5f        // cutoff in sigma units; exp(-10.125) ~ 4e-5
#define NPIX (RES * RES * 3)
#define NTILES ((RES / TILE_X) * (RES / TILE_Y))

// Scratch (no allocations allowed): partial images + per-tile arrival counters.
__device__ float g_part[2][NPIX];
__device__ unsigned int g_cnt[NTILES];   // zero-init at load; reset by 2nd arriver

// ---------------------------------------------------------------------------
// Render: one CTA per (32x16 tile, blob-half). 128 threads (32x4); 4 px/thread.
// Per-batch: prefetch raw blob (2 float4), derive splat constants in-register,
// ballot/prefix-compact tile survivors into shared, 2-way-unrolled evaluation
// with a per-column second-difference recurrence for the exponent:
//   a = (c*dx + s*dy)*kk/sx, b = (-s*dx + c*dy)*kk/sy, kk = sqrt(0.5*log2e)
//   g = 2^(-(a^2+b^2));  stepping y by BYD/RES: t += d; d += dd
// Tail: last-arriver CTA per tile fuses the two partials and writes out.
// ---------------------------------------------------------------------------
__global__ void __launch_bounds__(NT, 7) splat_render_kernel(
        const float* __restrict__ blobs, float* __restrict__ out) {
    __shared__ float4 sP[NT][3];
    __shared__ int sWarp[NT / 32];
    __shared__ unsigned int sArrive;

    const int tx = threadIdx.x;            // 0..31
    const int ty = threadIdx.y;            // 0..3
    const int tid = ty * BXD + tx;
    const int lane = tid & 31;
    const int wid = tid >> 5;
    const int z = blockIdx.z;
    const int blobBase = z * HALF;
    const int tile = blockIdx.y * gridDim.x + blockIdx.x;

    const int x = blockIdx.x * TILE_X + tx;
    const int y0 = blockIdx.y * TILE_Y + ty;
    const float inv = 1.0f / (float)RES;
    const float px = ((float)x + 0.5f) * inv;
    const float py = ((float)y0 + 0.5f) * inv;

    const float tX0 = (float)blockIdx.x * ((float)TILE_X * inv);
    const float tX1 = tX0 + (float)TILE_X * inv;
    const float tY0 = (float)blockIdx.y * ((float)TILE_Y * inv);
    const float tY1 = tY0 + (float)TILE_Y * inv;

    float aR[PPT], aG[PPT], aB[PPT];
#pragma unroll
    for (int k = 0; k < PPT; ++k) { aR[k] = 0.0f; aG[k] = 0.0f; aB[k] = 0.0f; }

    // Prefetch batch 0 raw blob (8 floats).
    const float4* __restrict__ blobs4 = (const float4*)blobs;
    float4 r0 = blobs4[(blobBase + tid) * 2 + 0];
    float4 r1 = blobs4[(blobBase + tid) * 2 + 1];

    for (int base = 0; base < HALF; base += NT) {
        // Derive splat constants for this thread's blob of the current batch.
        const float bx = r0.x, by = r0.y, sx = r0.z, sy = r0.w;
        const float rot = r1.x;
        float s, c;
        __sincosf(rot, &s, &c);
        const float kk = 0.84932180f;                  // sqrt(0.5*log2(e))
        const float isx = __fdividef(kk, sx);
        const float isy = __fdividef(kk, sy);
        const float A = c * isx, B = s * isx;
        const float C = -s * isy, D = c * isy;
        const float dlt = (float)BYD * inv;
        const float da = B * dlt, db = D * dlt;
        const float m1 = -2.0f * da, m2 = -2.0f * db;
        const float c0 = -(da * da + db * db);
        const float cc = c * c, ss = s * s;
        const float sx2 = sx * sx, sy2 = sy * sy;
        const float ex = QCUT * sqrtf(fmaf(cc, sx2, ss * sy2));
        const float ey = QCUT * sqrtf(fmaf(ss, sx2, cc * sy2));

        const bool keep = (bx + ex >= tX0) && (bx - ex <= tX1) &&
                          (by + ey >= tY0) && (by - ey <= tY1);

        const unsigned m = __ballot_sync(0xffffffffu, keep);
        if (lane == 0) sWarp[wid] = __popc(m);
        __syncthreads();

        int off = 0, total = 0;
#pragma unroll
        for (int w = 0; w < NT / 32; ++w) {
            int cw = sWarp[w];
            if (w < wid) off += cw;
            total += cw;
        }

        if (keep) {
            const int slot = off + __popc(m & ((1u << lane) - 1u));
            sP[slot][0] = make_float4(bx, by, A, B);
            sP[slot][1] = make_float4(C, D, m1, m2);
            sP[slot][2] = make_float4(r1.y, r1.z, r1.w, c0);
        }
        __syncthreads();

        // Prefetch next batch's raw blob (latency hidden behind the j-loop).
        const int nb = base + NT;
        if (nb < HALF) {
            const int i2 = blobBase + nb + tid;
            r0 = blobs4[i2 * 2 + 0];
            r1 = blobs4[i2 * 2 + 1];
        }

#define PAIR_BODY(J)                                                          \
        {                                                                     \
            const float4 p0 = sP[(J)][0];                                     \
            const float4 p1 = sP[(J)][1];                                     \
            const float4 p2 = sP[(J)][2];                                     \
            const float dx = px - p0.x;                                       \
            const float dy = py - p0.y;                                       \
            float a = fmaf(p0.z, dx, p0.w * dy);                              \
            float b = fmaf(p1.x, dx, p1.y * dy);                              \
            float t = fmaf(a, -a, -b * b);                                    \
            float d = fmaf(a, p1.z, fmaf(b, p1.w, p2.w));                     \
            const float dd = p2.w + p2.w;                                     \
            _Pragma("unroll")                                                 \
            for (int k = 0; k < PPT; ++k) {                                   \
                float g;                                                      \
                asm("ex2.approx.ftz.f32 %0, %1;" : "=f"(g) : "f"(t));         \
                aR[k] = fmaf(g, p2.x, aR[k]);                                 \
                aG[k] = fmaf(g, p2.y, aG[k]);                                 \
                aB[k] = fmaf(g, p2.z, aB[k]);                                 \
                if (k < PPT - 1) { t += d; d += dd; }                         \
            }                                                                 \
        }

        int j = 0;
        for (; j + 2 <= total; j += 2) {
            PAIR_BODY(j)
            PAIR_BODY(j + 1)
        }
        if (j < total) {
            PAIR_BODY(j)
        }
#undef PAIR_BODY

        __syncthreads();  // protect sP / sWarp before next batch rewrites them
    }

    // ---- Fused combine (last-block pattern, no spin; deadlock-free) ----
    // 1) publish this CTA's partial
    {
        int idx = (y0 * RES + x) * 3;
        float* __restrict__ mine = g_part[z];
#pragma unroll
        for (int k = 0; k < PPT; ++k) {
            mine[idx + 0] = aR[k];
            mine[idx + 1] = aG[k];
            mine[idx + 2] = aB[k];
            idx += BYD * RES * 3;
        }
    }
    __threadfence();
    __syncthreads();
    // 2) arrival count
    if (tid == 0) sArrive = atomicAdd(&g_cnt[tile], 1u);
    __syncthreads();
    if (sArrive == 1u) {
        // We are second: peer's partial is published. Add and write final.
        __threadfence();   // acquire: order peer's data before our reads
        const float* __restrict__ peer = g_part[z ^ 1];
        int idx = (y0 * RES + x) * 3;
#pragma unroll
        for (int k = 0; k < PPT; ++k) {
            out[idx + 0] = aR[k] + peer[idx + 0];
            out[idx + 1] = aG[k] + peer[idx + 1];
            out[idx + 2] = aB[k] + peer[idx + 2];
            idx += BYD * RES * 3;
        }
        __syncthreads();
        if (tid == 0) g_cnt[tile] = 0u;    // reset for next graph replay
    }
}

extern "C" void kernel_launch(void* const* d_in, const int* in_sizes, int n_in,
                              void* d_out, int out_size) {
    (void)in_sizes; (void)n_in; (void)out_size;
    const float* blobs = (const float*)d_in[0];
    float* out = (float*)d_out;

    dim3 grid(RES / TILE_X, RES / TILE_Y, 2);   // 16 x 32 tiles x 2 blob halves
    dim3 block(BXD, BYD);
    splat_render_kernel<<<grid, block>>>(blobs, out);
}

// round 11
// speedup vs baseline: 1.3633x; 1.0654x over previous
#include <cuda_runtime.h>

#define RES 512
#define NBLOBS 2048
#define HALF (NBLOBS / 2)
#define TILE_X 32
#define TILE_Y 16
#define BXD 32
#define BYD 4
#define NT 128           // threads per CTA
#define PPT 4            // pixels per thread (stride BYD rows)
#define QCUT 4.0f        // cutoff in sigma units; exp(-8) ~ 3.3e-4
#define NPIX (RES * RES * 3)
#define NTILES ((RES / TILE_X) * (RES / TILE_Y))

// Scratch (no allocations allowed): partial images + per-tile arrival counters.
__device__ float g_part[2][NPIX];
__device__ unsigned int g_cnt[NTILES];   // zero-init at load; reset by 2nd arriver

// Packed f32x2 helpers (FFMA2 path — ptxas never emits this from C++).
#define FMA2(acc, g, c) \
    asm("fma.rn.f32x2 %0, %1, %2, %0;" : "+l"(acc) : "l"(g), "l"(c))
#define PACK2(out, lo, hi) \
    asm("mov.b64 %0, {%1, %2};" : "=l"(out) : "f"(lo), "f"(hi))
#define UNPACK2(lo, hi, in) \
    asm("mov.b64 {%0, %1}, %2;" : "=f"(lo), "=f"(hi) : "l"(in))

// ---------------------------------------------------------------------------
// Render: one CTA per (32x16 tile, blob-half). 128 threads (32x4); 4 px/thread.
// Per-batch: prefetch raw blob (2 float4), derive splat constants in-register,
// ballot/prefix-compact tile survivors into shared (colors pre-duplicated for
// packed math), 2-way-unrolled evaluation with a second-difference recurrence
// for the exponent and f32x2-packed RGB accumulation:
//   a = (c*dx + s*dy)*kk/sx, b = (-s*dx + c*dy)*kk/sy, kk = sqrt(0.5*log2e)
//   g = 2^(-(a^2+b^2));  stepping y by BYD/RES: t += d; d += dd
// Tail: last-arriver CTA per tile fuses the two partials and writes out.
// ---------------------------------------------------------------------------
__global__ void __launch_bounds__(NT, 7) splat_render_kernel(
        const float* __restrict__ blobs, float* __restrict__ out) {
    __shared__ float4 sP[NT][4];
    __shared__ int sWarp[NT / 32];
    __shared__ unsigned int sArrive;

    const int tx = threadIdx.x;            // 0..31
    const int ty = threadIdx.y;            // 0..3
    const int tid = ty * BXD + tx;
    const int lane = tid & 31;
    const int wid = tid >> 5;
    const int z = blockIdx.z;
    const int blobBase = z * HALF;
    const int tile = blockIdx.y * gridDim.x + blockIdx.x;

    const int x = blockIdx.x * TILE_X + tx;
    const int y0 = blockIdx.y * TILE_Y + ty;
    const float inv = 1.0f / (float)RES;
    const float px = ((float)x + 0.5f) * inv;
    const float py = ((float)y0 + 0.5f) * inv;

    const float tX0 = (float)blockIdx.x * ((float)TILE_X * inv);
    const float tX1 = tX0 + (float)TILE_X * inv;
    const float tY0 = (float)blockIdx.y * ((float)TILE_Y * inv);
    const float tY1 = tY0 + (float)TILE_Y * inv;

    // Packed accumulators: (k0,k1) and (k2,k3) pixel pairs for R,G,B.
    unsigned long long accR01 = 0ull, accR23 = 0ull;
    unsigned long long accG01 = 0ull, accG23 = 0ull;
    unsigned long long accB01 = 0ull, accB23 = 0ull;

    // Prefetch batch 0 raw blob (8 floats).
    const float4* __restrict__ blobs4 = (const float4*)blobs;
    float4 r0 = blobs4[(blobBase + tid) * 2 + 0];
    float4 r1 = blobs4[(blobBase + tid) * 2 + 1];

    for (int base = 0; base < HALF; base += NT) {
        // Derive splat constants for this thread's blob of the current batch.
        const float bx = r0.x, by = r0.y, sx = r0.z, sy = r0.w;
        const float rot = r1.x;
        float s, c;
        __sincosf(rot, &s, &c);
        const float kk = 0.84932180f;                  // sqrt(0.5*log2(e))
        const float isx = __fdividef(kk, sx);
        const float isy = __fdividef(kk, sy);
        const float A = c * isx, B = s * isx;
        const float C = -s * isy, D = c * isy;
        const float dlt = (float)BYD * inv;
        const float da = B * dlt, db = D * dlt;
        const float m1 = -2.0f * da, m2 = -2.0f * db;
        const float c0 = -(da * da + db * db);
        const float cc = c * c, ss = s * s;
        const float sx2 = sx * sx, sy2 = sy * sy;
        const float ex = QCUT * sqrtf(fmaf(cc, sx2, ss * sy2));
        const float ey = QCUT * sqrtf(fmaf(ss, sx2, cc * sy2));

        const bool keep = (bx + ex >= tX0) && (bx - ex <= tX1) &&
                          (by + ey >= tY0) && (by - ey <= tY1);

        const unsigned m = __ballot_sync(0xffffffffu, keep);
        if (lane == 0) sWarp[wid] = __popc(m);
        __syncthreads();

        int off = 0, total = 0;
#pragma unroll
        for (int w = 0; w < NT / 32; ++w) {
            int cw = sWarp[w];
            if (w < wid) off += cw;
            total += cw;
        }

        if (keep) {
            const int slot = off + __popc(m & ((1u << lane) - 1u));
            sP[slot][0] = make_float4(bx, by, A, B);
            sP[slot][1] = make_float4(C, D, m1, m2);
            sP[slot][2] = make_float4(r1.y, r1.y, r1.z, r1.z);  // (r,r,g,g)
            sP[slot][3] = make_float4(r1.w, r1.w, c0, 0.0f);    // (b,b,c0,-)
        }
        __syncthreads();

        // Prefetch next batch's raw blob (latency hidden behind the j-loop).
        const int nb = base + NT;
        if (nb < HALF) {
            const int i2 = blobBase + nb + tid;
            r0 = blobs4[i2 * 2 + 0];
            r1 = blobs4[i2 * 2 + 1];
        }

#define PAIR_BODY(J)                                                          \
        {                                                                     \
            const float4 p0 = sP[(J)][0];                                     \
            const float4 p1 = sP[(J)][1];                                     \
            const ulonglong2 pc =                                             \
                *reinterpret_cast<const ulonglong2*>(&sP[(J)][2]);            \
            const float4 p3 = sP[(J)][3];                                     \
            const float dx = px - p0.x;                                       \
            const float dy = py - p0.y;                                       \
            float a = fmaf(p0.z, dx, p0.w * dy);                              \
            float b = fmaf(p1.x, dx, p1.y * dy);                              \
            float t = fmaf(a, -a, -b * b);                                    \
            float d = fmaf(a, p1.z, fmaf(b, p1.w, p3.z));                     \
            const float dd = p3.z + p3.z;                                     \
            float g0, g1, g2, g3;                                             \
            asm("ex2.approx.ftz.f32 %0, %1;" : "=f"(g0) : "f"(t));            \
            t += d; d += dd;                                                  \
            asm("ex2.approx.ftz.f32 %0, %1;" : "=f"(g1) : "f"(t));            \
            t += d; d += dd;                                                  \
            asm("ex2.approx.ftz.f32 %0, %1;" : "=f"(g2) : "f"(t));            \
            t += d;                                                           \
            asm("ex2.approx.ftz.f32 %0, %1;" : "=f"(g3) : "f"(t));            \
            unsigned long long G01, G23, BB;                                  \
            PACK2(G01, g0, g1);                                               \
            PACK2(G23, g2, g3);                                               \
            PACK2(BB, p3.x, p3.y);                                            \
            FMA2(accR01, G01, pc.x);                                          \
            FMA2(accR23, G23, pc.x);                                          \
            FMA2(accG01, G01, pc.y);                                          \
            FMA2(accG23, G23, pc.y);                                          \
            FMA2(accB01, G01, BB);                                            \
            FMA2(accB23, G23, BB);                                            \
        }

        int j = 0;
        for (; j + 2 <= total; j += 2) {
            PAIR_BODY(j)
            PAIR_BODY(j + 1)
        }
        if (j < total) {
            PAIR_BODY(j)
        }
#undef PAIR_BODY

        __syncthreads();  // protect sP / sWarp before next batch rewrites them
    }

    // Unpack accumulators.
    float aR[PPT], aG[PPT], aB[PPT];
    UNPACK2(aR[0], aR[1], accR01);
    UNPACK2(aR[2], aR[3], accR23);
    UNPACK2(aG[0], aG[1], accG01);
    UNPACK2(aG[2], aG[3], accG23);
    UNPACK2(aB[0], aB[1], accB01);
    UNPACK2(aB[2], aB[3], accB23);

    // ---- Fused combine (last-block pattern, no spin; deadlock-free) ----
    {
        int idx = (y0 * RES + x) * 3;
        float* __restrict__ mine = g_part[z];
#pragma unroll
        for (int k = 0; k < PPT; ++k) {
            mine[idx + 0] = aR[k];
            mine[idx + 1] = aG[k];
            mine[idx + 2] = aB[k];
            idx += BYD * RES * 3;
        }
    }
    __threadfence();
    __syncthreads();
    if (tid == 0) sArrive = atomicAdd(&g_cnt[tile], 1u);
    __syncthreads();
    if (sArrive == 1u) {
        __threadfence();   // acquire: order peer's data before our reads
        const float* __restrict__ peer = g_part[z ^ 1];
        int idx = (y0 * RES + x) * 3;
#pragma unroll
        for (int k = 0; k < PPT; ++k) {
            out[idx + 0] = aR[k] + peer[idx + 0];
            out[idx + 1] = aG[k] + peer[idx + 1];
            out[idx + 2] = aB[k] + peer[idx + 2];
            idx += BYD * RES * 3;
        }
        __syncthreads();
        if (tid == 0) g_cnt[tile] = 0u;    // reset for next graph replay
    }
}

extern "C" void kernel_launch(void* const* d_in, const int* in_sizes, int n_in,
                              void* d_out, int out_size) {
    (void)in_sizes; (void)n_in; (void)out_size;
    const float* blobs = (const float*)d_in[0];
    float* out = (float*)d_out;

    dim3 grid(RES / TILE_X, RES / TILE_Y, 2);   // 16 x 32 tiles x 2 blob halves
    dim3 block(BXD, BYD);
    splat_render_kernel<<<grid, block>>>(blobs, out);
}

// round 12
// speedup vs baseline: 1.4180x; 1.0401x over previous
#include <cuda_runtime.h>

#define RES 512
#define NBLOBS 2048
#define NSPLIT 4
#define QUART (NBLOBS / NSPLIT)
#define TILE_X 32
#define TILE_Y 16
#define BXD 32
#define BYD 4
#define NT 128           // threads per CTA
#define PPT 4            // pixels per thread (stride BYD rows)
#define QCUT 3.75f       // cutoff in sigma units; exp(-7.03) ~ 8.8e-4
#define NPIX (RES * RES * 3)
#define NTILES ((RES / TILE_X) * (RES / TILE_Y))

// Scratch (no allocations allowed): partial images + per-tile arrival counters.
__device__ float g_part[NSPLIT][NPIX];
__device__ unsigned int g_cnt[NTILES];   // zero-init at load; reset by last arriver

// Packed f32x2 helpers (FFMA2 path — ptxas never emits this from C++).
#define FMA2(acc, g, c) \
    asm("fma.rn.f32x2 %0, %1, %2, %0;" : "+l"(acc) : "l"(g), "l"(c))
#define PACK2(out, lo, hi) \
    asm("mov.b64 %0, {%1, %2};" : "=l"(out) : "f"(lo), "f"(hi))
#define UNPACK2(lo, hi, in) \
    asm("mov.b64 {%0, %1}, %2;" : "=f"(lo), "=f"(hi) : "l"(in))

// ---------------------------------------------------------------------------
// Render: one CTA per (32x16 tile, blob-quarter). 128 threads; 4 px/thread.
// Per-batch: prefetch raw blob (2 float4), derive splat constants in-register,
// ballot/prefix-compact tile survivors into shared (colors pre-duplicated,
// c0/2c0 pre-packed), 2-way-unrolled evaluation with a second-difference
// recurrence for the exponent and f32x2-packed RGB accumulation:
//   a = A*px + B*py + P,  b = C*px + D*py + Q   (P,Q fold in the blob center)
//   g = 2^(-(a^2+b^2));  stepping y by BYD/RES: t += d; d += dd
// Tail: last-arriver CTA per tile fuses the four partials and writes out.
// ---------------------------------------------------------------------------
__global__ void __launch_bounds__(NT, 7) splat_render_kernel(
        const float* __restrict__ blobs, float* __restrict__ out) {
    __shared__ float4 sP[NT][4];
    __shared__ int sWarp[NT / 32];
    __shared__ unsigned int sArrive;

    const int tx = threadIdx.x;            // 0..31
    const int ty = threadIdx.y;            // 0..3
    const int tid = ty * BXD + tx;
    const int lane = tid & 31;
    const int wid = tid >> 5;
    const int z = blockIdx.z;
    const int blobBase = z * QUART;
    const int tile = blockIdx.y * gridDim.x + blockIdx.x;

    const int x = blockIdx.x * TILE_X + tx;
    const int y0 = blockIdx.y * TILE_Y + ty;
    const float inv = 1.0f / (float)RES;
    const float px = ((float)x + 0.5f) * inv;
    const float py = ((float)y0 + 0.5f) * inv;

    const float tX0 = (float)blockIdx.x * ((float)TILE_X * inv);
    const float tX1 = tX0 + (float)TILE_X * inv;
    const float tY0 = (float)blockIdx.y * ((float)TILE_Y * inv);
    const float tY1 = tY0 + (float)TILE_Y * inv;

    // Packed accumulators: (k0,k1) and (k2,k3) pixel pairs for R,G,B.
    unsigned long long accR01 = 0ull, accR23 = 0ull;
    unsigned long long accG01 = 0ull, accG23 = 0ull;
    unsigned long long accB01 = 0ull, accB23 = 0ull;

    // Prefetch batch 0 raw blob (8 floats).
    const float4* __restrict__ blobs4 = (const float4*)blobs;
    float4 r0 = blobs4[(blobBase + tid) * 2 + 0];
    float4 r1 = blobs4[(blobBase + tid) * 2 + 1];

    for (int base = 0; base < QUART; base += NT) {
        // Derive splat constants for this thread's blob of the current batch.
        const float bx = r0.x, by = r0.y, sx = r0.z, sy = r0.w;
        const float rot = r1.x;
        float s, c;
        __sincosf(rot, &s, &c);
        const float kk = 0.84932180f;                  // sqrt(0.5*log2(e))
        const float isx = __fdividef(kk, sx);
        const float isy = __fdividef(kk, sy);
        const float A = c * isx, B = s * isx;
        const float C = -s * isy, D = c * isy;
        const float P = -fmaf(A, bx, B * by);          // fold center into offset
        const float Q = -fmaf(C, bx, D * by);
        const float dlt = (float)BYD * inv;
        const float da = B * dlt, db = D * dlt;
        const float m1 = -2.0f * da, m2 = -2.0f * db;
        const float c0 = -(da * da + db * db);
        const float cc = c * c, ss = s * s;
        const float sx2 = sx * sx, sy2 = sy * sy;
        const float ex = QCUT * sqrtf(fmaf(cc, sx2, ss * sy2));
        const float ey = QCUT * sqrtf(fmaf(ss, sx2, cc * sy2));

        const bool keep = (bx + ex >= tX0) && (bx - ex <= tX1) &&
                          (by + ey >= tY0) && (by - ey <= tY1);

        const unsigned m = __ballot_sync(0xffffffffu, keep);
        if (lane == 0) sWarp[wid] = __popc(m);
        __syncthreads();

        int off = 0, total = 0;
#pragma unroll
        for (int w = 0; w < NT / 32; ++w) {
            int cw = sWarp[w];
            if (w < wid) off += cw;
            total += cw;
        }

        if (keep) {
            const int slot = off + __popc(m & ((1u << lane) - 1u));
            sP[slot][0] = make_float4(A, B, C, D);
            sP[slot][1] = make_float4(P, Q, m1, m2);
            sP[slot][2] = make_float4(r1.y, r1.y, r1.z, r1.z);       // (r,r,g,g)
            sP[slot][3] = make_float4(r1.w, r1.w, c0, c0 + c0);      // (b,b,c0,2c0)
        }
        __syncthreads();

        // Prefetch next batch's raw blob (latency hidden behind the j-loop).
        const int nb = base + NT;
        if (nb < QUART) {
            const int i2 = blobBase + nb + tid;
            r0 = blobs4[i2 * 2 + 0];
            r1 = blobs4[i2 * 2 + 1];
        }

#define PAIR_BODY(J)                                                          \
        {                                                                     \
            const float4 p0 = sP[(J)][0];                                     \
            const float4 p1 = sP[(J)][1];                                     \
            const ulonglong2 pc =                                             \
                *reinterpret_cast<const ulonglong2*>(&sP[(J)][2]);            \
            const ulonglong2 q3 =                                             \
                *reinterpret_cast<const ulonglong2*>(&sP[(J)][3]);            \
            float c0f, ddf;                                                   \
            UNPACK2(c0f, ddf, q3.y);                                          \
            float a = fmaf(p0.x, px, fmaf(p0.y, py, p1.x));                   \
            float b = fmaf(p0.z, px, fmaf(p0.w, py, p1.y));                   \
            float t = fmaf(a, -a, -b * b);                                    \
            float d = fmaf(a, p1.z, fmaf(b, p1.w, c0f));                      \
            float g0, g1, g2, g3;                                             \
            asm("ex2.approx.ftz.f32 %0, %1;" : "=f"(g0) : "f"(t));            \
            t += d; d += ddf;                                                 \
            asm("ex2.approx.ftz.f32 %0, %1;" : "=f"(g1) : "f"(t));            \
            t += d; d += ddf;                                                 \
            asm("ex2.approx.ftz.f32 %0, %1;" : "=f"(g2) : "f"(t));            \
            t += d;                                                           \
            asm("ex2.approx.ftz.f32 %0, %1;" : "=f"(g3) : "f"(t));            \
            unsigned long long G01, G23;                                      \
            PACK2(G01, g0, g1);                                               \
            PACK2(G23, g2, g3);                                               \
            FMA2(accR01, G01, pc.x);                                          \
            FMA2(accR23, G23, pc.x);                                          \
            FMA2(accG01, G01, pc.y);                                          \
            FMA2(accG23, G23, pc.y);                                          \
            FMA2(accB01, G01, q3.x);                                          \
            FMA2(accB23, G23, q3.x);                                          \
        }

        int j = 0;
        for (; j + 2 <= total; j += 2) {
            PAIR_BODY(j)
            PAIR_BODY(j + 1)
        }
        if (j < total) {
            PAIR_BODY(j)
        }
#undef PAIR_BODY

        __syncthreads();  // protect sP / sWarp before next batch rewrites them
    }

    // Unpack accumulators.
    float aR[PPT], aG[PPT], aB[PPT];
    UNPACK2(aR[0], aR[1], accR01);
    UNPACK2(aR[2], aR[3], accR23);
    UNPACK2(aG[0], aG[1], accG01);
    UNPACK2(aG[2], aG[3], accG23);
    UNPACK2(aB[0], aB[1], accB01);
    UNPACK2(aB[2], aB[3], accB23);

    // ---- Fused combine (last-block pattern, no spin; deadlock-free) ----
    {
        int idx = (y0 * RES + x) * 3;
        float* __restrict__ mine = g_part[z];
#pragma unroll
        for (int k = 0; k < PPT; ++k) {
            mine[idx + 0] = aR[k];
            mine[idx + 1] = aG[k];
            mine[idx + 2] = aB[k];
            idx += BYD * RES * 3;
        }
    }
    __threadfence();
    __syncthreads();
    if (tid == 0) sArrive = atomicAdd(&g_cnt[tile], 1u);
    __syncthreads();
    if (sArrive == NSPLIT - 1u) {
        // We are last: all peers' partials are published (L2-resident).
        __threadfence();   // acquire: order peers' data before our reads
        const float* __restrict__ pA = g_part[(z + 1) & (NSPLIT - 1)];
        const float* __restrict__ pB = g_part[(z + 2) & (NSPLIT - 1)];
        const float* __restrict__ pC = g_part[(z + 3) & (NSPLIT - 1)];
        int idx = (y0 * RES + x) * 3;
#pragma unroll
        for (int k = 0; k < PPT; ++k) {
            out[idx + 0] = aR[k] + pA[idx + 0] + (pB[idx + 0] + pC[idx + 0]);
            out[idx + 1] = aG[k] + pA[idx + 1] + (pB[idx + 1] + pC[idx + 1]);
            out[idx + 2] = aB[k] + pA[idx + 2] + (pB[idx + 2] + pC[idx + 2]);
            idx += BYD * RES * 3;
        }
        __syncthreads();
        if (tid == 0) g_cnt[tile] = 0u;    // reset for next graph replay
    }
}

extern "C" void kernel_launch(void* const* d_in, const int* in_sizes, int n_in,
                              void* d_out, int out_size) {
    (void)in_sizes; (void)n_in; (void)out_size;
    const float* blobs = (const float*)d_in[0];
    float* out = (float*)d_out;

    dim3 grid(RES / TILE_X, RES / TILE_Y, NSPLIT);  // 16 x 32 tiles x 4 quarters
    dim3 block(BXD, BYD);
    splat_render_kernel<<<grid, block>>>(blobs, out);
}

// round 13
// speedup vs baseline: 1.5039x; 1.0606x over previous
#include <cuda_runtime.h>

#define RES 512
#define NBLOBS 2048
#define NSPLIT 4
#define QUART (NBLOBS / NSPLIT)
#define TILE_X 32
#define TILE_Y 16
#define BXD 32
#define BYD 4
#define NT 128           // threads per CTA
#define PPT 4            // pixels per thread (stride BYD rows)
#define QCUT 3.75f       // cutoff in sigma units; exp(-7.03) ~ 8.8e-4
#define QCUT2 (QCUT * QCUT)
#define NPIX (RES * RES * 3)
#define NTILES ((RES / TILE_X) * (RES / TILE_Y))

// Scratch (no allocations allowed): partial images + per-tile arrival counters.
__device__ float g_part[NSPLIT][NPIX];
__device__ unsigned int g_cnt[NTILES];   // zero-init at load; reset by last arriver

// Packed f32x2 helpers (FFMA2 path — ptxas never emits this from C++).
#define FMA2(acc, g, c) \
    asm("fma.rn.f32x2 %0, %1, %2, %0;" : "+l"(acc) : "l"(g), "l"(c))
#define PACK2(out, lo, hi) \
    asm("mov.b64 %0, {%1, %2};" : "=l"(out) : "f"(lo), "f"(hi))
#define UNPACK2(lo, hi, in) \
    asm("mov.b64 {%0, %1}, %2;" : "=f"(lo), "=f"(hi) : "l"(in))

// ---------------------------------------------------------------------------
// Render: one CTA per (32x16 tile, blob-quarter). 128 threads; 4 px/thread.
// Per-batch: prefetch raw blob (2 float4), derive splat constants in-register,
// cull via exact disk-vs-box test in the blob's whitened (a,b) frame,
// ballot/prefix-compact survivors into shared (colors pre-duplicated, c0/2c0
// pre-packed), 2-way-unrolled evaluation with a second-difference recurrence
// for the exponent and f32x2-packed RGB accumulation:
//   a = A*px + B*py + P,  b = C*px + D*py + Q   (P,Q fold in the blob center)
//   g = 2^(-(a^2+b^2));  stepping y by BYD/RES: t += d; d += dd
// Tail: last-arriver CTA per tile fuses the four partials and writes out.
// ---------------------------------------------------------------------------
__global__ void __launch_bounds__(NT, 8) splat_render_kernel(
        const float* __restrict__ blobs, float* __restrict__ out) {
    __shared__ float4 sP[NT][4];
    __shared__ int sWarp[NT / 32];
    __shared__ unsigned int sArrive;

    const int tx = threadIdx.x;            // 0..31
    const int ty = threadIdx.y;            // 0..3
    const int tid = ty * BXD + tx;
    const int lane = tid & 31;
    const int wid = tid >> 5;
    const int z = blockIdx.z;
    const int blobBase = z * QUART;
    const int tile = blockIdx.y * gridDim.x + blockIdx.x;

    const int x = blockIdx.x * TILE_X + tx;
    const int y0 = blockIdx.y * TILE_Y + ty;
    const float inv = 1.0f / (float)RES;
    const float px = ((float)x + 0.5f) * inv;
    const float py = ((float)y0 + 0.5f) * inv;

    // Tile center and half-extents in normalized coords.
    const float hx = 0.5f * (float)TILE_X * inv;
    const float hy = 0.5f * (float)TILE_Y * inv;
    const float tcx = (float)blockIdx.x * ((float)TILE_X * inv) + hx;
    const float tcy = (float)blockIdx.y * ((float)TILE_Y * inv) + hy;

    // Packed accumulators: (k0,k1) and (k2,k3) pixel pairs for R,G,B.
    unsigned long long accR01 = 0ull, accR23 = 0ull;
    unsigned long long accG01 = 0ull, accG23 = 0ull;
    unsigned long long accB01 = 0ull, accB23 = 0ull;

    // Prefetch batch 0 raw blob (8 floats).
    const float4* __restrict__ blobs4 = (const float4*)blobs;
    float4 r0 = blobs4[(blobBase + tid) * 2 + 0];
    float4 r1 = blobs4[(blobBase + tid) * 2 + 1];

    for (int base = 0; base < QUART; base += NT) {
        // Derive splat constants for this thread's blob of the current batch.
        const float bx = r0.x, by = r0.y, sx = r0.z, sy = r0.w;
        const float rot = r1.x;
        float s, c;
        __sincosf(rot, &s, &c);
        const float kk = 0.84932180f;                  // sqrt(0.5*log2(e))
        const float isx = __fdividef(kk, sx);
        const float isy = __fdividef(kk, sy);
        const float A = c * isx, B = s * isx;
        const float C = -s * isy, D = c * isy;
        const float P = -fmaf(A, bx, B * by);          // fold center into offset
        const float Q = -fmaf(C, bx, D * by);
        const float dlt = (float)BYD * inv;
        const float da_ = B * dlt, db_ = D * dlt;
        const float m1 = -2.0f * da_, m2 = -2.0f * db_;
        const float c0 = -(da_ * da_ + db_ * db_);

        // Cull: tile -> interval box in (a,b); keep iff the box intersects the
        // disk a^2+b^2 <= (QCUT*kk)^2. Note a,b already carry the kk factor,
        // so the radius in this frame is QCUT*kk.
        const float ac = fmaf(A, tcx, fmaf(B, tcy, P));
        const float bc = fmaf(C, tcx, fmaf(D, tcy, Q));
        const float ra = fabsf(A) * hx + fabsf(B) * hy;
        const float rb = fabsf(C) * hx + fabsf(D) * hy;
        const float dA = fmaxf(fabsf(ac) - ra, 0.0f);
        const float dB = fmaxf(fabsf(bc) - rb, 0.0f);
        const float rad2 = QCUT2 * (kk * kk);
        const bool keep = fmaf(dA, dA, dB * dB) <= rad2;

        const unsigned m = __ballot_sync(0xffffffffu, keep);
        if (lane == 0) sWarp[wid] = __popc(m);
        __syncthreads();

        int off = 0, total = 0;
#pragma unroll
        for (int w = 0; w < NT / 32; ++w) {
            int cw = sWarp[w];
            if (w < wid) off += cw;
            total += cw;
        }

        if (keep) {
            const int slot = off + __popc(m & ((1u << lane) - 1u));
            sP[slot][0] = make_float4(A, B, C, D);
            sP[slot][1] = make_float4(P, Q, m1, m2);
            sP[slot][2] = make_float4(r1.y, r1.y, r1.z, r1.z);       // (r,r,g,g)
            sP[slot][3] = make_float4(r1.w, r1.w, c0, c0 + c0);      // (b,b,c0,2c0)
        }
        __syncthreads();

        // Prefetch next batch's raw blob (latency hidden behind the j-loop).
        const int nb = base + NT;
        if (nb < QUART) {
            const int i2 = blobBase + nb + tid;
            r0 = blobs4[i2 * 2 + 0];
            r1 = blobs4[i2 * 2 + 1];
        }

#define PAIR_BODY(J)                                                          \
        {                                                                     \
            const float4 p0 = sP[(J)][0];                                     \
            const float4 p1 = sP[(J)][1];                                     \
            const ulonglong2 pc =                                             \
                *reinterpret_cast<const ulonglong2*>(&sP[(J)][2]);            \
            const ulonglong2 q3 =                                             \
                *reinterpret_cast<const ulonglong2*>(&sP[(J)][3]);            \
            float c0f, ddf;                                                   \
            UNPACK2(c0f, ddf, q3.y);                                          \
            float a = fmaf(p0.x, px, fmaf(p0.y, py, p1.x));                   \
            float b = fmaf(p0.z, px, fmaf(p0.w, py, p1.y));                   \
            float t = fmaf(a, -a, -b * b);                                    \
            float d = fmaf(a, p1.z, fmaf(b, p1.w, c0f));                      \
            float g0, g1, g2, g3;                                             \
            asm("ex2.approx.ftz.f32 %0, %1;" : "=f"(g0) : "f"(t));            \
            t += d; d += ddf;                                                 \
            asm("ex2.approx.ftz.f32 %0, %1;" : "=f"(g1) : "f"(t));            \
            t += d; d += ddf;                                                 \
            asm("ex2.approx.ftz.f32 %0, %1;" : "=f"(g2) : "f"(t));            \
            t += d;                                                           \
            asm("ex2.approx.ftz.f32 %0, %1;" : "=f"(g3) : "f"(t));            \
            unsigned long long G01, G23;                                      \
            PACK2(G01, g0, g1);                                               \
            PACK2(G23, g2, g3);                                               \
            FMA2(accR01, G01, pc.x);                                          \
            FMA2(accR23, G23, pc.x);                                          \
            FMA2(accG01, G01, pc.y);                                          \
            FMA2(accG23, G23, pc.y);                                          \
            FMA2(accB01, G01, q3.x);                                          \
            FMA2(accB23, G23, q3.x);                                          \
        }

        int j = 0;
        for (; j + 2 <= total; j += 2) {
            PAIR_BODY(j)
            PAIR_BODY(j + 1)
        }
        if (j < total) {
            PAIR_BODY(j)
        }
#undef PAIR_BODY

        __syncthreads();  // protect sP / sWarp before next batch rewrites them
    }

    // Unpack accumulators.
    float aR[PPT], aG[PPT], aB[PPT];
    UNPACK2(aR[0], aR[1], accR01);
    UNPACK2(aR[2], aR[3], accR23);
    UNPACK2(aG[0], aG[1], accG01);
    UNPACK2(aG[2], aG[3], accG23);
    UNPACK2(aB[0], aB[1], accB01);
    UNPACK2(aB[2], aB[3], accB23);

    // ---- Fused combine (last-block pattern, no spin; deadlock-free) ----
    {
        int idx = (y0 * RES + x) * 3;
        float* __restrict__ mine = g_part[z];
#pragma unroll
        for (int k = 0; k < PPT; ++k) {
            mine[idx + 0] = aR[k];
            mine[idx + 1] = aG[k];
            mine[idx + 2] = aB[k];
            idx += BYD * RES * 3;
        }
    }
    __threadfence();
    __syncthreads();
    if (tid == 0) sArrive = atomicAdd(&g_cnt[tile], 1u);
    __syncthreads();
    if (sArrive == NSPLIT - 1u) {
        // We are last: all peers' partials are published (L2-resident).
        __threadfence();   // acquire: order peers' data before our reads
        const float* __restrict__ pA = g_part[(z + 1) & (NSPLIT - 1)];
        const float* __restrict__ pB = g_part[(z + 2) & (NSPLIT - 1)];
        const float* __restrict__ pC = g_part[(z + 3) & (NSPLIT - 1)];
        int idx = (y0 * RES + x) * 3;
#pragma unroll
        for (int k = 0; k < PPT; ++k) {
            out[idx + 0] = aR[k] + pA[idx + 0] + (pB[idx + 0] + pC[idx + 0]);
            out[idx + 1] = aG[k] + pA[idx + 1] + (pB[idx + 1] + pC[idx + 1]);
            out[idx + 2] = aB[k] + pA[idx + 2] + (pB[idx + 2] + pC[idx + 2]);
            idx += BYD * RES * 3;
        }
        __syncthreads();
        if (tid == 0) g_cnt[tile] = 0u;    // reset for next graph replay
    }
}

extern "C" void kernel_launch(void* const* d_in, const int* in_sizes, int n_in,
                              void* d_out, int out_size) {
    (void)in_sizes; (void)n_in; (void)out_size;
    const float* blobs = (const float*)d_in[0];
    float* out = (float*)d_out;

    dim3 grid(RES / TILE_X, RES / TILE_Y, NSPLIT);  // 16 x 32 tiles x 4 quarters
    dim3 block(BXD, BYD);
    splat_render_kernel<<<grid, block>>>(blobs, out);
}